// round 4
// baseline (speedup 1.0000x reference)
#include <cuda_runtime.h>

// Problem constants (fixed by reference)
#define NB      8192
#define ND      256
#define MAXPOS  1536                  // max same-label partners per row (mean 512, sd ~22)
#define INV_T   14.285714285714286f   // 1 / 0.07
#define EPSL    1e-8f

// Scratch (allocation-free: __device__ globals)
__device__ float g_negsum[NB];
__device__ int   g_poscnt[NB];
__device__ float g_pos[(size_t)NB * MAXPOS];   // 48 MB
__device__ float g_total;
__device__ int   g_nvalid;
__device__ int   g_is64;

// ---------------------------------------------------------------------------
// k_init: zero accumulators + detect label dtype (int64 vs int32).
// If labels are int64 (values 0..15), every odd 32-bit word is 0.
// ---------------------------------------------------------------------------
__global__ void k_init(const int* __restrict__ lab32) {
    int i = blockIdx.x * blockDim.x + threadIdx.x;
    if (i < NB) { g_negsum[i] = 0.0f; g_poscnt[i] = 0; }
    if (i == 0) {
        g_total = 0.0f;
        g_nvalid = 0;
        int all0 = 1;
        #pragma unroll 1
        for (int t = 1; t < 128; t += 2) {
            if (lab32[t] != 0) { all0 = 0; break; }
        }
        g_is64 = all0;
    }
}

// ---------------------------------------------------------------------------
// k_main: fused 128x128-tile SGEMM (sim = F F^T / T) + epilogue.
// grid = (8 column-chunks of 1024, 64 row-tiles of 128), 256 threads.
// Per CTA: rows [rowBase, rowBase+128), cols [colChunk, colChunk+1024).
// Epilogue per 128x128 tile:
//   - negatives: negpart[row] += expf(s)
//   - positives: reserve slots in g_pos[row] via smem-aggregated atomics
// ---------------------------------------------------------------------------
__global__ void __launch_bounds__(256) k_main(const float* __restrict__ feats,
                                              const void*  __restrict__ labels) {
    __shared__ float As[16][128];
    __shared__ float Bs[16][128];
    __shared__ int   lblR[128], lblC[128];
    __shared__ int   tileCnt[128], tileBase[128];
    __shared__ float negred[128];
    __shared__ int   s_is64;

    const int tid = threadIdx.x;
    const int tx  = tid & 15;       // 0..15  -> column micro-tile
    const int ty  = tid >> 4;       // 0..15  -> row micro-tile
    const int rowBase  = blockIdx.y * 128;
    const int colChunk = blockIdx.x * 1024;
    const int r0 = ty * 8;          // first local row of this thread
    const int c0 = tx * 8;          // first local col of this thread

    if (tid == 0) s_is64 = g_is64;
    __syncthreads();
    const int is64 = s_is64;

    if (tid < 128) {
        lblR[tid] = is64 ? (int)((const long long*)labels)[rowBase + tid]
                         : ((const int*)labels)[rowBase + tid];
    }

    float negpart[8];
    #pragma unroll
    for (int i = 0; i < 8; i++) negpart[i] = 0.0f;

    const int lr_ = tid >> 1;          // 0..127: row loaded by this thread
    const int kq_ = (tid & 1) * 8;     // 0 or 8: k-offset loaded

    for (int tile = 0; tile < 8; tile++) {
        const int colBase = colChunk + tile * 128;
        __syncthreads();   // previous tile's epilogue fully done before reuse
        if (tid < 128) {
            lblC[tid] = is64 ? (int)((const long long*)labels)[colBase + tid]
                             : ((const int*)labels)[colBase + tid];
            tileCnt[tid] = 0;
        }

        float acc[8][8];
        #pragma unroll
        for (int i = 0; i < 8; i++)
            #pragma unroll
            for (int j = 0; j < 8; j++) acc[i][j] = 0.0f;

        for (int kt = 0; kt < ND; kt += 16) {
            __syncthreads();
            {
                const float* ap = &feats[(size_t)(rowBase + lr_) * ND + kt + kq_];
                float4 v0 = *(const float4*)ap;
                float4 v1 = *(const float4*)(ap + 4);
                As[kq_ + 0][lr_] = v0.x; As[kq_ + 1][lr_] = v0.y;
                As[kq_ + 2][lr_] = v0.z; As[kq_ + 3][lr_] = v0.w;
                As[kq_ + 4][lr_] = v1.x; As[kq_ + 5][lr_] = v1.y;
                As[kq_ + 6][lr_] = v1.z; As[kq_ + 7][lr_] = v1.w;

                const float* bp = &feats[(size_t)(colBase + lr_) * ND + kt + kq_];
                float4 w0 = *(const float4*)bp;
                float4 w1 = *(const float4*)(bp + 4);
                Bs[kq_ + 0][lr_] = w0.x; Bs[kq_ + 1][lr_] = w0.y;
                Bs[kq_ + 2][lr_] = w0.z; Bs[kq_ + 3][lr_] = w0.w;
                Bs[kq_ + 4][lr_] = w1.x; Bs[kq_ + 5][lr_] = w1.y;
                Bs[kq_ + 6][lr_] = w1.z; Bs[kq_ + 7][lr_] = w1.w;
            }
            __syncthreads();
            #pragma unroll
            for (int k = 0; k < 16; k++) {
                float a[8], b[8];
                float4 a0 = *(const float4*)&As[k][r0];
                float4 a1 = *(const float4*)&As[k][r0 + 4];
                float4 b0 = *(const float4*)&Bs[k][c0];
                float4 b1 = *(const float4*)&Bs[k][c0 + 4];
                a[0]=a0.x; a[1]=a0.y; a[2]=a0.z; a[3]=a0.w;
                a[4]=a1.x; a[5]=a1.y; a[6]=a1.z; a[7]=a1.w;
                b[0]=b0.x; b[1]=b0.y; b[2]=b0.z; b[3]=b0.w;
                b[4]=b1.x; b[5]=b1.y; b[6]=b1.z; b[7]=b1.w;
                #pragma unroll
                for (int i = 0; i < 8; i++)
                    #pragma unroll
                    for (int j = 0; j < 8; j++)
                        acc[i][j] = fmaf(a[i], b[j], acc[i][j]);
            }
        }

        // ---- epilogue: classify the 128x128 tile ----
        // Phase 1: negatives -> negpart; count positives, reserve smem slots.
        int myoff[8];
        #pragma unroll
        for (int i = 0; i < 8; i++) {
            const int r    = r0 + i;
            const int grow = rowBase + r;
            const int lr   = lblR[r];
            int n = 0;
            #pragma unroll
            for (int j = 0; j < 8; j++) {
                const int gcol = colBase + c0 + j;
                if (grow == gcol) continue;                 // diagonal excluded
                if (lr != lblC[c0 + j])
                    negpart[i] += __expf(acc[i][j] * INV_T);
                else
                    n++;
            }
            myoff[i] = n ? atomicAdd(&tileCnt[r], n) : 0;
        }
        __syncthreads();
        // Phase 2: one global reservation per row per tile.
        if (tid < 128) {
            int c = tileCnt[tid];
            tileBase[tid] = c ? atomicAdd(&g_poscnt[rowBase + tid], c) : 0;
        }
        __syncthreads();
        // Phase 3: scatter positive s-values.
        #pragma unroll
        for (int i = 0; i < 8; i++) {
            const int r    = r0 + i;
            const int grow = rowBase + r;
            const int lr   = lblR[r];
            int w = tileBase[r] + myoff[i];
            #pragma unroll
            for (int j = 0; j < 8; j++) {
                const int gcol = colBase + c0 + j;
                if (grow == gcol) continue;
                if (lr == lblC[c0 + j]) {
                    if (w < MAXPOS)
                        g_pos[(size_t)grow * MAXPOS + w] = acc[i][j] * INV_T;
                    w++;
                }
            }
        }
    }

    // ---- per-row neg_sum: reduce across the 16 threads sharing each row ----
    __syncthreads();
    if (tid < 128) negred[tid] = 0.0f;
    __syncthreads();
    #pragma unroll
    for (int i = 0; i < 8; i++) atomicAdd(&negred[r0 + i], negpart[i]);
    __syncthreads();
    if (tid < 128) atomicAdd(&g_negsum[rowBase + tid], negred[tid]);
}

// ---------------------------------------------------------------------------
// k_rows: warp per row. row_loss = (1/num_pos) * sum_pos -log(e/(e+neg)+eps)
// valid rows accumulate into g_total / g_nvalid.
// ---------------------------------------------------------------------------
__global__ void k_rows() {
    const int gtid = blockIdx.x * blockDim.x + threadIdx.x;
    const int row  = gtid >> 5;
    const int lane = gtid & 31;
    if (row >= NB) return;

    const float neg = g_negsum[row];
    const int   np  = g_poscnt[row];
    const int   m   = np < MAXPOS ? np : MAXPOS;

    float s = 0.0f;
    for (int t = lane; t < m; t += 32) {
        float e = __expf(g_pos[(size_t)row * MAXPOS + t]);
        s -= __logf(__fdividef(e, e + neg) + EPSL);
    }
    #pragma unroll
    for (int o = 16; o > 0; o >>= 1)
        s += __shfl_xor_sync(0xffffffffu, s, o);

    if (lane == 0) {
        const int nneg = NB - 1 - np;
        if (np > 0 && nneg > 0) {
            atomicAdd(&g_total, s / (float)np);
            atomicAdd(&g_nvalid, 1);
        }
    }
}

__global__ void k_out(float* out) {
    out[0] = (g_nvalid > 0) ? g_total / (float)g_nvalid : 0.0f;
}

// ---------------------------------------------------------------------------
extern "C" void kernel_launch(void* const* d_in, const int* in_sizes, int n_in,
                              void* d_out, int out_size) {
    const float* feats  = (const float*)d_in[0];
    const void*  labels = d_in[1];

    k_init<<<(NB + 255) / 256, 256>>>((const int*)labels);

    dim3 grid(8, 64);          // 8 column chunks x 64 row tiles = 512 CTAs
    k_main<<<grid, 256>>>(feats, labels);

    k_rows<<<(NB * 32) / 256, 256>>>();   // 8192 warps, one per row
    k_out<<<1, 1>>>((float*)d_out);
}

// round 6
// speedup vs baseline: 2.7798x; 2.7798x over previous
#include <cuda_runtime.h>
#include <cuda_bf16.h>
#include <cstdint>

// Problem constants
#define NB      8192
#define ND      256
#define MAXPOS  1536
#define INV_T   14.285714285714286f
#define EPSL    1e-8f
#define NT      4              // col tiles per CTA
#define ROWSTR  528            // smem row stride in bytes (256 bf16 + 16B pad)

// ---- scratch (__device__ globals; no allocation) ----
__device__ float          g_negsum[NB];
__device__ int            g_poscnt[NB];
__device__ float          g_pos[(size_t)NB * MAXPOS];    // 48 MB
__device__ float          g_total;
__device__ int            g_nvalid;
__device__ int            g_is64;
__device__ __nv_bfloat16  g_fbf[(size_t)NB * ND];        // 4 MB bf16 features

// ============================ helpers ============================
__device__ __forceinline__ uint32_t smem_u32(const void* p) {
    uint32_t a;
    asm("{ .reg .u64 t; cvta.to.shared.u64 t, %1; cvt.u32.u64 %0, t; }" : "=r"(a) : "l"(p));
    return a;
}

__device__ __forceinline__ void ldsm_x4(uint32_t* r, uint32_t addr) {
    asm volatile("ldmatrix.sync.aligned.m8n8.x4.shared.b16 {%0,%1,%2,%3}, [%4];"
                 : "=r"(r[0]), "=r"(r[1]), "=r"(r[2]), "=r"(r[3]) : "r"(addr));
}

__device__ __forceinline__ void mma16816(float* c, const uint32_t* a,
                                         uint32_t b0, uint32_t b1) {
    asm volatile(
        "mma.sync.aligned.m16n8k16.row.col.f32.bf16.bf16.f32 "
        "{%0,%1,%2,%3}, {%4,%5,%6,%7}, {%8,%9}, {%0,%1,%2,%3};"
        : "+f"(c[0]), "+f"(c[1]), "+f"(c[2]), "+f"(c[3])
        : "r"(a[0]), "r"(a[1]), "r"(a[2]), "r"(a[3]), "r"(b0), "r"(b1));
}

// ============================ small kernels ============================
__global__ void k_init(const int* __restrict__ lab32) {
    int i = blockIdx.x * blockDim.x + threadIdx.x;
    if (i < NB) { g_negsum[i] = 0.0f; g_poscnt[i] = 0; }
    if (i == 0) {
        g_total = 0.0f; g_nvalid = 0;
        int all0 = 1;
        #pragma unroll 1
        for (int t = 1; t < 128; t += 2)
            if (lab32[t] != 0) { all0 = 0; break; }
        g_is64 = all0;     // int64 labels (0..15) -> odd words all zero
    }
}

__global__ void k_prep(const float* __restrict__ f) {
    int i = blockIdx.x * blockDim.x + threadIdx.x;   // over NB*ND/2
    float2 v = ((const float2*)f)[i];
    ((__nv_bfloat162*)g_fbf)[i] = __floats2bfloat162_rn(v.x, v.y);
}

// ============================ main fused kernel ============================
// dyn smem: A tile [128 x ROWSTR], B tiles [2][128 x ROWSTR]
#define SM_A   0
#define SM_B0  (128 * ROWSTR)
#define SM_B1  (2 * 128 * ROWSTR)
#define SM_TOT (3 * 128 * ROWSTR)     // 202,752 B

extern __shared__ char dsm[];

__global__ void __launch_bounds__(256, 1) k_main(const void* __restrict__ labels) {
    __shared__ int   lblR[128];
    __shared__ int   lblC[2][128];
    __shared__ int   tileCnt[128], tileBase[128];
    __shared__ float negred[128];
    __shared__ int   s_is64;

    const int tid  = threadIdx.x;
    const int warp = tid >> 5;
    const int lane = tid & 31;
    const int warpRow = warp & 3;          // 4 row-bands of 32
    const int warpCol = warp >> 2;         // 2 col-bands of 64
    const int rowBase  = blockIdx.y * 128;
    const int colChunk = blockIdx.x * (NT * 128);

    const uint32_t smb = smem_u32(dsm);

    if (tid == 0) s_is64 = g_is64;
    __syncthreads();
    const int is64 = s_is64;

    if (tid < 128) {
        lblR[tid] = is64 ? (int)((const long long*)labels)[rowBase + tid]
                         : ((const int*)labels)[rowBase + tid];
        tileCnt[tid] = 0;
    }

    // ---- load A tile (128 rows x 256 bf16) ----
    {
        const uint4* src = (const uint4*)(g_fbf + (size_t)rowBase * ND);
        #pragma unroll
        for (int i = 0; i < 16; i++) {
            int u = tid + i * 256;             // 0..4095
            int row = u >> 5, q = u & 31;      // q: 16B chunk
            *(uint4*)(dsm + SM_A + row * ROWSTR + q * 16) = src[(size_t)row * 32 + q];
        }
    }

    auto loadB = [&](int buf, int t) {
        const int colBase = colChunk + t * 128;
        const uint4* src = (const uint4*)(g_fbf + (size_t)colBase * ND);
        char* dst = dsm + (buf ? SM_B1 : SM_B0);
        #pragma unroll
        for (int i = 0; i < 16; i++) {
            int u = tid + i * 256;
            int row = u >> 5, q = u & 31;
            *(uint4*)(dst + row * ROWSTR + q * 16) = src[(size_t)row * 32 + q];
        }
        if (tid < 128)
            lblC[buf][tid] = is64 ? (int)((const long long*)labels)[colBase + tid]
                                  : ((const int*)labels)[colBase + tid];
    };

    // per-thread ldmatrix base addresses (k offset added per step)
    // A: lanes 0-7: m+0..7 k0 | 8-15: m+8..15 k0 | 16-23: m+0..7 k8 | 24-31: m+8..15 k8
    const uint32_t aBase = smb + SM_A
        + (uint32_t)(warpRow * 32 + (lane & 15)) * ROWSTR + ((lane >> 4) * 8) * 2;
    // B: lanes 0-7: n+0..7 k0 | 8-15: n+0..7 k8 | 16-23: n+8..15 k0 | 24-31: n+8..15 k8
    const uint32_t bRowOff =
        (uint32_t)(warpCol * 64 + (lane & 7) + ((lane >> 4) << 3)) * ROWSTR
        + (((lane >> 3) & 1) * 8) * 2;

    // epilogue mapping: 4 rows per thread (mt,h), 16 cols per row
    int   rloc[4];
    #pragma unroll
    for (int idx = 0; idx < 4; idx++)
        rloc[idx] = warpRow * 32 + (idx >> 1) * 16 + (idx & 1) * 8 + (lane >> 2);
    float negPart[4] = {0.f, 0.f, 0.f, 0.f};

    // ---- prologue ----
    loadB(0, 0);
    __syncthreads();

    for (int t = 0; t < NT; t++) {
        const int buf     = t & 1;
        const int colBase = colChunk + t * 128;

        if (t + 1 < NT) loadB(buf ^ 1, t + 1);   // prefetch next tile

        // ---- GEMM: 32x64 per warp over K=256 ----
        float acc[2][8][4];
        #pragma unroll
        for (int mt = 0; mt < 2; mt++)
            #pragma unroll
            for (int nt = 0; nt < 8; nt++)
                #pragma unroll
                for (int c = 0; c < 4; c++) acc[mt][nt][c] = 0.0f;

        const uint32_t bBase = (buf ? smb + SM_B1 : smb + SM_B0) + bRowOff;

        #pragma unroll
        for (int ks = 0; ks < 16; ks++) {
            const uint32_t koff = ks * 32;   // 16 bf16 = 32 B
            uint32_t a[2][4], b[4][4];
            ldsm_x4(a[0], aBase + koff);
            ldsm_x4(a[1], aBase + 16 * ROWSTR + koff);
            #pragma unroll
            for (int np = 0; np < 4; np++)
                ldsm_x4(b[np], bBase + np * 16 * ROWSTR + koff);
            #pragma unroll
            for (int mt = 0; mt < 2; mt++)
                #pragma unroll
                for (int nt = 0; nt < 8; nt++)
                    mma16816(acc[mt][nt], a[mt],
                             b[nt >> 1][(nt & 1) * 2], b[nt >> 1][(nt & 1) * 2 + 1]);
        }

        // ---- epilogue: classify 128x128 tile ----
        // acc[mt][nt][h*2+e] = sim(row = wr*32+mt*16+h*8+lane/4,
        //                          col = wc*64+nt*8+2*(lane&3)+e)
        int myoff[4];
        #pragma unroll
        for (int idx = 0; idx < 4; idx++) {
            const int mt = idx >> 1, h = idx & 1;
            const int r    = rloc[idx];
            const int grow = rowBase + r;
            const int lr   = lblR[r];
            int cnt = 0;
            #pragma unroll
            for (int nt = 0; nt < 8; nt++) {
                #pragma unroll
                for (int e = 0; e < 2; e++) {
                    const int col  = warpCol * 64 + nt * 8 + 2 * (lane & 3) + e;
                    const int gcol = colBase + col;
                    if (gcol == grow) continue;
                    if (lblC[buf][col] != lr)
                        negPart[idx] += __expf(acc[mt][nt][h * 2 + e] * INV_T);
                    else cnt++;
                }
            }
            myoff[idx] = cnt ? atomicAdd(&tileCnt[r], cnt) : 0;
        }
        __syncthreads();
        if (tid < 128) {
            int c = tileCnt[tid];
            tileBase[tid] = c ? atomicAdd(&g_poscnt[rowBase + tid], c) : 0;
            tileCnt[tid] = 0;
        }
        __syncthreads();
        #pragma unroll
        for (int idx = 0; idx < 4; idx++) {
            const int mt = idx >> 1, h = idx & 1;
            const int r    = rloc[idx];
            const int grow = rowBase + r;
            const int lr   = lblR[r];
            int w = tileBase[r] + myoff[idx];
            #pragma unroll
            for (int nt = 0; nt < 8; nt++) {
                #pragma unroll
                for (int e = 0; e < 2; e++) {
                    const int col  = warpCol * 64 + nt * 8 + 2 * (lane & 3) + e;
                    const int gcol = colBase + col;
                    if (gcol == grow) continue;
                    if (lblC[buf][col] == lr) {
                        if (w < MAXPOS)
                            g_pos[(size_t)grow * MAXPOS + w] =
                                acc[mt][nt][h * 2 + e] * INV_T;
                        w++;
                    }
                }
            }
        }
        __syncthreads();   // tileBase consumed; B[buf^1] + lblC published for next tile
    }

    // ---- per-row neg reduction ----
    if (tid < 128) negred[tid] = 0.0f;
    __syncthreads();
    #pragma unroll
    for (int idx = 0; idx < 4; idx++) atomicAdd(&negred[rloc[idx]], negPart[idx]);
    __syncthreads();
    if (tid < 128) atomicAdd(&g_negsum[rowBase + tid], negred[tid]);
}

// ---------------------------------------------------------------------------
__global__ void k_rows() {
    const int gtid = blockIdx.x * blockDim.x + threadIdx.x;
    const int row  = gtid >> 5;
    const int lane = gtid & 31;
    if (row >= NB) return;

    const float neg = g_negsum[row];
    const int   np  = g_poscnt[row];
    const int   m   = np < MAXPOS ? np : MAXPOS;

    float s = 0.0f;
    for (int t = lane; t < m; t += 32) {
        float e = __expf(g_pos[(size_t)row * MAXPOS + t]);
        s -= __logf(__fdividef(e, e + neg) + EPSL);
    }
    #pragma unroll
    for (int o = 16; o > 0; o >>= 1)
        s += __shfl_xor_sync(0xffffffffu, s, o);

    if (lane == 0) {
        const int nneg = NB - 1 - np;
        if (np > 0 && nneg > 0) {
            atomicAdd(&g_total, s / (float)np);
            atomicAdd(&g_nvalid, 1);
        }
    }
}

__global__ void k_out(float* out) {
    out[0] = (g_nvalid > 0) ? g_total / (float)g_nvalid : 0.0f;
}

// ---------------------------------------------------------------------------
extern "C" void kernel_launch(void* const* d_in, const int* in_sizes, int n_in,
                              void* d_out, int out_size) {
    const float* feats  = (const float*)d_in[0];
    const void*  labels = d_in[1];

    cudaFuncSetAttribute(k_main, cudaFuncAttributeMaxDynamicSharedMemorySize, SM_TOT);

    k_init<<<(NB + 255) / 256, 256>>>((const int*)labels);
    k_prep<<<(NB * ND / 2) / 256, 256>>>(feats);

    dim3 grid(NB / (NT * 128), NB / 128);   // (16, 64) = 1024 CTAs
    k_main<<<grid, 256, SM_TOT>>>(labels);

    k_rows<<<(NB * 32) / 256, 256>>>();
    k_out<<<1, 1>>>((float*)d_out);
}

// round 8
// speedup vs baseline: 3.6249x; 1.3040x over previous
#include <cuda_runtime.h>
#include <cuda_bf16.h>
#include <cstdint>

// Problem constants
#define NB      8192
#define ND      256
#define MAXPOS  1536
#define INV_T   14.285714285714286f
#define EXC     20.617439059314203f   // INV_T * log2(e)
#define LOG2E   1.4426950408889634f
#define EPSL    1e-8f
#define NT      4                     // col tiles per CTA
#define ROWSTR  528                   // smem row stride (256 bf16 + 16B pad)

// ---- scratch (__device__ globals; no allocation) ----
__device__ float          g_negsum[NB];
__device__ int            g_poscnt[NB];
__device__ float          g_pos[(size_t)NB * MAXPOS];    // 48 MB
__device__ float          g_total;
__device__ int            g_nvalid;
__device__ int            g_is64;
__device__ __nv_bfloat16  g_fbf[(size_t)NB * ND];        // 4 MB bf16 features

// ============================ helpers ============================
__device__ __forceinline__ uint32_t smem_u32(const void* p) {
    uint32_t a;
    asm("{ .reg .u64 t; cvta.to.shared.u64 t, %1; cvt.u32.u64 %0, t; }" : "=r"(a) : "l"(p));
    return a;
}
__device__ __forceinline__ void ldsm_x4(uint32_t* r, uint32_t addr) {
    asm volatile("ldmatrix.sync.aligned.m8n8.x4.shared.b16 {%0,%1,%2,%3}, [%4];"
                 : "=r"(r[0]), "=r"(r[1]), "=r"(r[2]), "=r"(r[3]) : "r"(addr));
}
__device__ __forceinline__ void mma16816(float* c, const uint32_t* a,
                                         uint32_t b0, uint32_t b1) {
    asm volatile(
        "mma.sync.aligned.m16n8k16.row.col.f32.bf16.bf16.f32 "
        "{%0,%1,%2,%3}, {%4,%5,%6,%7}, {%8,%9}, {%0,%1,%2,%3};"
        : "+f"(c[0]), "+f"(c[1]), "+f"(c[2]), "+f"(c[3])
        : "r"(a[0]), "r"(a[1]), "r"(a[2]), "r"(a[3]), "r"(b0), "r"(b1));
}
__device__ __forceinline__ void cp16(uint32_t dst, const void* src) {
    asm volatile("cp.async.cg.shared.global [%0], [%1], 16;" :: "r"(dst), "l"(src));
}
#define CP_COMMIT() asm volatile("cp.async.commit_group;" ::: "memory")
#define CP_WAIT0()  asm volatile("cp.async.wait_group 0;" ::: "memory")
__device__ __forceinline__ float ex2(float x) {
    float y; asm("ex2.approx.ftz.f32 %0, %1;" : "=f"(y) : "f"(x)); return y;
}

// ============================ small kernels ============================
__global__ void k_init(const int* __restrict__ lab32) {
    int i = blockIdx.x * blockDim.x + threadIdx.x;
    if (i < NB) { g_negsum[i] = 0.0f; g_poscnt[i] = 0; }
    if (i == 0) {
        g_total = 0.0f; g_nvalid = 0;
        int all0 = 1;
        #pragma unroll 1
        for (int t = 1; t < 128; t += 2)
            if (lab32[t] != 0) { all0 = 0; break; }
        g_is64 = all0;     // int64 labels (0..15) -> odd words all zero
    }
}

__global__ void k_prep(const float* __restrict__ f) {
    int i = blockIdx.x * blockDim.x + threadIdx.x;   // over NB*ND/2
    float2 v = ((const float2*)f)[i];
    ((__nv_bfloat162*)g_fbf)[i] = __floats2bfloat162_rn(v.x, v.y);
}

// ============================ main fused kernel ============================
#define SM_A   0
#define SM_B0  (128 * ROWSTR)
#define SM_B1  (2 * 128 * ROWSTR)
#define SM_TOT (3 * 128 * ROWSTR)     // 202,752 B

extern __shared__ char dsm[];

__global__ void __launch_bounds__(512, 1) k_main(const void* __restrict__ labels) {
    __shared__ int   lblR[128];
    __shared__ int   lblC[2][128];
    __shared__ float negred[128];
    __shared__ int   s_is64;

    const int tid  = threadIdx.x;
    const int warp = tid >> 5;
    const int lane = tid & 31;
    const int warpRow = warp & 3;          // 4 row-bands of 32
    const int warpCol = warp >> 2;         // 4 col-bands of 32
    const int rowBase  = blockIdx.y * 128;
    const int colChunk = blockIdx.x * (NT * 128);

    const uint32_t smb = smem_u32(dsm);

    if (tid == 0) s_is64 = g_is64;
    __syncthreads();
    const int is64 = s_is64;

    if (tid < 128)
        lblR[tid] = is64 ? (int)((const long long*)labels)[rowBase + tid]
                         : ((const int*)labels)[rowBase + tid];

    // ---- async load A tile + B tile 0 (each 4096 x 16B; 8 per thread) ----
    {
        const uint4* srcA = (const uint4*)(g_fbf + (size_t)rowBase * ND);
        const uint4* srcB = (const uint4*)(g_fbf + (size_t)colChunk * ND);
        #pragma unroll
        for (int i = 0; i < 8; i++) {
            int u = tid + i * 512;                 // 0..4095
            int row = u >> 5, q = u & 31;
            cp16(smb + SM_A  + row * ROWSTR + q * 16, srcA + u);
            cp16(smb + SM_B0 + row * ROWSTR + q * 16, srcB + u);
        }
        CP_COMMIT();
    }
    if (tid < 128)
        lblC[0][tid] = is64 ? (int)((const long long*)labels)[colChunk + tid]
                            : ((const int*)labels)[colChunk + tid];
    CP_WAIT0();
    __syncthreads();

    // per-thread ldmatrix bases
    const uint32_t aBase = smb + SM_A
        + (uint32_t)(warpRow * 32 + (lane & 15)) * ROWSTR + ((lane >> 4) * 8) * 2;
    const uint32_t bRowOff =
        (uint32_t)(warpCol * 32 + (lane & 7) + ((lane >> 4) << 3)) * ROWSTR
        + (((lane >> 3) & 1) * 8) * 2;

    // 4 rows per thread: idx -> (mt = idx>>1, h = idx&1)
    int rloc[4];
    #pragma unroll
    for (int idx = 0; idx < 4; idx++)
        rloc[idx] = warpRow * 32 + (idx >> 1) * 16 + (idx & 1) * 8 + (lane >> 2);
    float negPart[4] = {0.f, 0.f, 0.f, 0.f};

    for (int t = 0; t < NT; t++) {
        const int buf     = t & 1;
        const int colBase = colChunk + t * 128;

        // prefetch next B tile + labels (fully async under GEMM+epilogue)
        if (t + 1 < NT) {
            const int nb = colBase + 128;
            const uint4* src = (const uint4*)(g_fbf + (size_t)nb * ND);
            const uint32_t dst = buf ? (smb + SM_B0) : (smb + SM_B1);
            #pragma unroll
            for (int i = 0; i < 8; i++) {
                int u = tid + i * 512;
                int row = u >> 5, q = u & 31;
                cp16(dst + row * ROWSTR + q * 16, src + u);
            }
            CP_COMMIT();
            if (tid < 128)
                lblC[buf ^ 1][tid] = is64 ? (int)((const long long*)labels)[nb + tid]
                                          : ((const int*)labels)[nb + tid];
        }

        // ---- GEMM: 32x32 per warp over K=256 ----
        float acc[2][4][4];
        #pragma unroll
        for (int mt = 0; mt < 2; mt++)
            #pragma unroll
            for (int nt = 0; nt < 4; nt++)
                #pragma unroll
                for (int c = 0; c < 4; c++) acc[mt][nt][c] = 0.0f;

        const uint32_t bBase = (buf ? smb + SM_B1 : smb + SM_B0) + bRowOff;

        #pragma unroll
        for (int ks = 0; ks < 16; ks++) {
            const uint32_t koff = ks * 32;       // 16 bf16 = 32 B
            uint32_t a[2][4], b[2][4];
            ldsm_x4(a[0], aBase + koff);
            ldsm_x4(a[1], aBase + 16 * ROWSTR + koff);
            ldsm_x4(b[0], bBase + koff);
            ldsm_x4(b[1], bBase + 16 * ROWSTR + koff);
            #pragma unroll
            for (int mt = 0; mt < 2; mt++)
                #pragma unroll
                for (int nt = 0; nt < 4; nt++)
                    mma16816(acc[mt][nt], a[mt],
                             b[nt >> 1][(nt & 1) * 2], b[nt >> 1][(nt & 1) * 2 + 1]);
        }

        // ---- epilogue: classify + direct-atomic scatter ----
        const bool diagTile = (colBase == rowBase);
        #pragma unroll
        for (int idx = 0; idx < 4; idx++) {
            const int mt = idx >> 1, h = idx & 1;
            const int r    = rloc[idx];
            const int grow = rowBase + r;
            const int lr   = lblR[r];
            uint32_t pmask = 0;
            float na = 0.0f;
            #pragma unroll
            for (int nt = 0; nt < 4; nt++) {
                #pragma unroll
                for (int e = 0; e < 2; e++) {
                    const int col = warpCol * 32 + nt * 8 + 2 * (lane & 3) + e;
                    if (diagTile && col == r) continue;
                    if (lblC[buf][col] != lr)
                        na += ex2(acc[mt][nt][h * 2 + e] * EXC);
                    else
                        pmask |= 1u << (nt * 2 + e);
                }
            }
            negPart[idx] += na;
            if (pmask) {
                int w = atomicAdd(&g_poscnt[grow], __popc(pmask));
                float* dst = &g_pos[(size_t)grow * MAXPOS];
                while (pmask) {
                    const int bpos = __ffs(pmask) - 1;
                    pmask &= pmask - 1;
                    if (w < MAXPOS)
                        dst[w] = acc[mt][bpos >> 1][h * 2 + (bpos & 1)] * INV_T;
                    w++;
                }
            }
        }

        if (t + 1 < NT) CP_WAIT0();
        __syncthreads();   // B[buf^1]+lblC visible; reads of buf done before overwrite
    }

    // ---- per-row neg reduction (16 threads share each row) ----
    if (tid < 128) negred[tid] = 0.0f;
    __syncthreads();
    #pragma unroll
    for (int idx = 0; idx < 4; idx++) atomicAdd(&negred[rloc[idx]], negPart[idx]);
    __syncthreads();
    if (tid < 128) atomicAdd(&g_negsum[rowBase + tid], negred[tid]);
}

// ---------------------------------------------------------------------------
// k_rows: warp per row, float4 chunks -> 4 independent MUFU chains per lane
__global__ void k_rows() {
    const int gtid = blockIdx.x * blockDim.x + threadIdx.x;
    const int row  = gtid >> 5;
    const int lane = gtid & 31;
    if (row >= NB) return;

    const float neg = g_negsum[row];
    const int   np  = g_poscnt[row];
    const int   m   = np < MAXPOS ? np : MAXPOS;

    const float4* rowp = (const float4*)&g_pos[(size_t)row * MAXPOS];
    float s = 0.0f;
    for (int c = lane; c * 4 < m; c += 32) {
        float4 v = rowp[c];
        const int base = c * 4;
        float vv[4] = {v.x, v.y, v.z, v.w};
        #pragma unroll
        for (int k = 0; k < 4; k++) {
            if (base + k < m) {
                float e = ex2(vv[k] * LOG2E);
                s -= __logf(__fdividef(e, e + neg) + EPSL);
            }
        }
    }
    #pragma unroll
    for (int o = 16; o > 0; o >>= 1)
        s += __shfl_xor_sync(0xffffffffu, s, o);

    if (lane == 0) {
        const int nneg = NB - 1 - np;
        if (np > 0 && nneg > 0) {
            atomicAdd(&g_total, s / (float)np);
            atomicAdd(&g_nvalid, 1);
        }
    }
}

__global__ void k_out(float* out) {
    out[0] = (g_nvalid > 0) ? g_total / (float)g_nvalid : 0.0f;
}

// ---------------------------------------------------------------------------
extern "C" void kernel_launch(void* const* d_in, const int* in_sizes, int n_in,
                              void* d_out, int out_size) {
    const float* feats  = (const float*)d_in[0];
    const void*  labels = d_in[1];

    cudaFuncSetAttribute(k_main, cudaFuncAttributeMaxDynamicSharedMemorySize, SM_TOT);

    k_init<<<(NB + 255) / 256, 256>>>((const int*)labels);
    k_prep<<<(NB * ND / 2) / 256, 256>>>(feats);

    dim3 grid(NB / (NT * 128), NB / 128);   // (16, 64) = 1024 CTAs
    k_main<<<grid, 512, SM_TOT>>>(labels);

    k_rows<<<(NB * 32) / 256, 256>>>();
    k_out<<<1, 1>>>((float*)d_out);
}

// round 11
// speedup vs baseline: 4.1582x; 1.1471x over previous
#include <cuda_runtime.h>
#include <cuda_bf16.h>
#include <cstdint>

// Problem constants
#define NB      8192
#define ND      256
#define MAXPOS  1536
#define INV_T   14.285714285714286f
#define EXC     20.617439059314203f   // INV_T * log2(e)
#define LOG2E   1.4426950408889634f
#define EPSL    1e-8f
#define NT      4                     // col tiles per CTA
#define ROWSTR  272                   // smem row stride (256 fp8 + 16B pad)

// ---- scratch (__device__ globals; no allocation) ----
__device__ float    g_negsum[NB];
__device__ int      g_poscnt[NB];
__device__ float    g_pos[(size_t)NB * MAXPOS];   // 48 MB
__device__ float    g_total;
__device__ int      g_nvalid;
__device__ int      g_is64;
__device__ uint8_t  g_f8[(size_t)NB * ND];        // 2 MB e4m3 features

// ============================ helpers ============================
__device__ __forceinline__ uint32_t smem_u32(const void* p) {
    uint32_t a;
    asm("{ .reg .u64 t; cvta.to.shared.u64 t, %1; cvt.u32.u64 %0, t; }" : "=r"(a) : "l"(p));
    return a;
}
__device__ __forceinline__ void ldsm_x4(uint32_t* r, uint32_t addr) {
    asm volatile("ldmatrix.sync.aligned.m8n8.x4.shared.b16 {%0,%1,%2,%3}, [%4];"
                 : "=r"(r[0]), "=r"(r[1]), "=r"(r[2]), "=r"(r[3]) : "r"(addr));
}
__device__ __forceinline__ void mma_fp8(float* c, const uint32_t* a,
                                        uint32_t b0, uint32_t b1) {
    asm volatile(
        "mma.sync.aligned.m16n8k32.row.col.f32.e4m3.e4m3.f32 "
        "{%0,%1,%2,%3}, {%4,%5,%6,%7}, {%8,%9}, {%0,%1,%2,%3};"
        : "+f"(c[0]), "+f"(c[1]), "+f"(c[2]), "+f"(c[3])
        : "r"(a[0]), "r"(a[1]), "r"(a[2]), "r"(a[3]), "r"(b0), "r"(b1));
}
__device__ __forceinline__ void cp16(uint32_t dst, const void* src) {
    asm volatile("cp.async.cg.shared.global [%0], [%1], 16;" :: "r"(dst), "l"(src));
}
#define CP_COMMIT() asm volatile("cp.async.commit_group;" ::: "memory")
#define CP_WAIT0()  asm volatile("cp.async.wait_group 0;" ::: "memory")
__device__ __forceinline__ float ex2(float x) {
    float y; asm("ex2.approx.ftz.f32 %0, %1;" : "=f"(y) : "f"(x)); return y;
}
// pack two f32 -> e4m3x2 (hi -> upper byte, lo -> lower byte)
__device__ __forceinline__ uint16_t cvt8x2(float hi, float lo) {
    uint16_t h;
    asm("cvt.rn.satfinite.e4m3x2.f32 %0, %1, %2;" : "=h"(h) : "f"(hi), "f"(lo));
    return h;
}

// ============================ small kernels ============================
__global__ void k_init(const int* __restrict__ lab32) {
    int i = blockIdx.x * blockDim.x + threadIdx.x;
    if (i < NB) { g_negsum[i] = 0.0f; g_poscnt[i] = 0; }
    if (i == 0) {
        g_total = 0.0f; g_nvalid = 0;
        int all0 = 1;
        #pragma unroll 1
        for (int t = 1; t < 128; t += 2)
            if (lab32[t] != 0) { all0 = 0; break; }
        g_is64 = all0;     // int64 labels (0..15) -> odd words all zero
    }
}

__global__ void k_prep(const float* __restrict__ f) {
    int i = blockIdx.x * blockDim.x + threadIdx.x;   // over NB*ND/4
    float4 v = ((const float4*)f)[i];
    uint32_t lo = cvt8x2(v.y, v.x);
    uint32_t hi = cvt8x2(v.w, v.z);
    ((uint32_t*)g_f8)[i] = lo | (hi << 16);
}

// ============================ main fused kernel ============================
#define SM_A   0
#define SM_B0  (128 * ROWSTR)
#define SM_B1  (2 * 128 * ROWSTR)
#define SM_TOT (3 * 128 * ROWSTR)     // 104,448 B -> 2 CTAs/SM

extern __shared__ char dsm[];

__global__ void __launch_bounds__(256, 2) k_main(const void* __restrict__ labels) {
    __shared__ int   lblR[128];
    __shared__ int   lblC[2][128];
    __shared__ float negred[128];
    __shared__ int   s_is64;

    const int tid  = threadIdx.x;
    const int warp = tid >> 5;
    const int lane = tid & 31;
    const int warpRow = warp & 3;          // 4 row-bands of 32
    const int warpCol = warp >> 2;         // 2 col-bands of 64
    const int rowBase  = blockIdx.y * 128;
    const int colChunk = blockIdx.x * (NT * 128);

    const uint32_t smb = smem_u32(dsm);

    if (tid == 0) s_is64 = g_is64;
    __syncthreads();
    const int is64 = s_is64;

    if (tid < 128)
        lblR[tid] = is64 ? (int)((const long long*)labels)[rowBase + tid]
                         : ((const int*)labels)[rowBase + tid];

    // ---- async load A tile + B tile 0 (each 128 rows x 256 B = 2048 x 16B) ----
    {
        const uint4* srcA = (const uint4*)(g_f8 + (size_t)rowBase * ND);
        const uint4* srcB = (const uint4*)(g_f8 + (size_t)colChunk * ND);
        #pragma unroll
        for (int i = 0; i < 8; i++) {
            int u = tid + i * 256;                 // 0..2047
            int row = u >> 4, q = u & 15;
            cp16(smb + SM_A  + row * ROWSTR + q * 16, srcA + u);
            cp16(smb + SM_B0 + row * ROWSTR + q * 16, srcB + u);
        }
        CP_COMMIT();
    }
    if (tid < 128)
        lblC[0][tid] = is64 ? (int)((const long long*)labels)[colChunk + tid]
                            : ((const int*)labels)[colChunk + tid];
    CP_WAIT0();
    __syncthreads();

    // ldmatrix bases (fp8 m16n8k32 fragments)
    // A x4 tiles: lanes 0-7: rows 0-7 k0-15 | 8-15: rows 8-15 k0-15
    //             | 16-23: rows 0-7 k16-31 | 24-31: rows 8-15 k16-31
    const uint32_t aBase = smb + SM_A
        + (uint32_t)(warpRow * 32 + ((lane >> 3) & 1) * 8 + (lane & 7)) * ROWSTR
        + (lane >> 4) * 16;
    // B x4 tiles: lanes 0-7: n0-7 k0-15 | 8-15: n0-7 k16-31
    //             | 16-23: n8-15 k0-15 | 24-31: n8-15 k16-31
    const uint32_t bRowOff =
        (uint32_t)(warpCol * 64 + (lane >> 4) * 8 + (lane & 7)) * ROWSTR
        + ((lane >> 3) & 1) * 16;

    // 4 rows per thread: idx -> (mt = idx>>1, h = idx&1)
    int rloc[4];
    #pragma unroll
    for (int idx = 0; idx < 4; idx++)
        rloc[idx] = warpRow * 32 + (idx >> 1) * 16 + (idx & 1) * 8 + (lane >> 2);
    float negPart[4] = {0.f, 0.f, 0.f, 0.f};

    for (int t = 0; t < NT; t++) {
        const int buf     = t & 1;
        const int colBase = colChunk + t * 128;

        // prefetch next B tile + labels (async under GEMM+epilogue)
        if (t + 1 < NT) {
            const int nb = colBase + 128;
            const uint4* src = (const uint4*)(g_f8 + (size_t)nb * ND);
            const uint32_t dst = buf ? (smb + SM_B0) : (smb + SM_B1);
            #pragma unroll
            for (int i = 0; i < 8; i++) {
                int u = tid + i * 256;
                int row = u >> 4, q = u & 15;
                cp16(dst + row * ROWSTR + q * 16, src + u);
            }
            CP_COMMIT();
            if (tid < 128)
                lblC[buf ^ 1][tid] = is64 ? (int)((const long long*)labels)[nb + tid]
                                          : ((const int*)labels)[nb + tid];
        }

        // ---- GEMM: 32x64 per warp over K=256 (8 k-steps of 32) ----
        float acc[2][8][4];
        #pragma unroll
        for (int mt = 0; mt < 2; mt++)
            #pragma unroll
            for (int nt = 0; nt < 8; nt++)
                #pragma unroll
                for (int c = 0; c < 4; c++) acc[mt][nt][c] = 0.0f;

        const uint32_t bBase = (buf ? smb + SM_B1 : smb + SM_B0) + bRowOff;

        #pragma unroll
        for (int ks = 0; ks < 8; ks++) {
            const uint32_t koff = ks * 32;       // 32 fp8 = 32 B
            uint32_t a[2][4], b[4][4];
            ldsm_x4(a[0], aBase + koff);
            ldsm_x4(a[1], aBase + 16 * ROWSTR + koff);
            #pragma unroll
            for (int nt2 = 0; nt2 < 4; nt2++)
                ldsm_x4(b[nt2], bBase + nt2 * 16 * ROWSTR + koff);
            #pragma unroll
            for (int mt = 0; mt < 2; mt++)
                #pragma unroll
                for (int nt = 0; nt < 8; nt++)
                    mma_fp8(acc[mt][nt], a[mt],
                            b[nt >> 1][(nt & 1) * 2], b[nt >> 1][(nt & 1) * 2 + 1]);
        }

        // ---- epilogue: classify + direct-atomic scatter ----
        const bool diagTile = (colBase == rowBase);
        #pragma unroll
        for (int idx = 0; idx < 4; idx++) {
            const int mt = idx >> 1, h = idx & 1;
            const int r    = rloc[idx];
            const int grow = rowBase + r;
            const int lr   = lblR[r];
            uint32_t pmask = 0;
            float na = 0.0f;
            #pragma unroll
            for (int nt = 0; nt < 8; nt++) {
                #pragma unroll
                for (int e = 0; e < 2; e++) {
                    const int col = warpCol * 64 + nt * 8 + 2 * (lane & 3) + e;
                    if (diagTile && col == r) continue;
                    if (lblC[buf][col] != lr)
                        na += ex2(acc[mt][nt][h * 2 + e] * EXC);
                    else
                        pmask |= 1u << (nt * 2 + e);
                }
            }
            negPart[idx] += na;
            if (pmask) {
                int w = atomicAdd(&g_poscnt[grow], __popc(pmask));
                float* dst = &g_pos[(size_t)grow * MAXPOS];
                while (pmask) {
                    const int bpos = __ffs(pmask) - 1;
                    pmask &= pmask - 1;
                    if (w < MAXPOS)
                        dst[w] = acc[mt][bpos >> 1][h * 2 + (bpos & 1)] * INV_T;
                    w++;
                }
            }
        }

        if (t + 1 < NT) CP_WAIT0();
        __syncthreads();   // B[buf^1]+lblC visible; reads of buf done before overwrite
    }

    // ---- per-row neg reduction (8 threads share each row) ----
    if (tid < 128) negred[tid] = 0.0f;
    __syncthreads();
    #pragma unroll
    for (int idx = 0; idx < 4; idx++) atomicAdd(&negred[rloc[idx]], negPart[idx]);
    __syncthreads();
    if (tid < 128) atomicAdd(&g_negsum[rowBase + tid], negred[tid]);
}

// ---------------------------------------------------------------------------
// k_rows: warp per row, float4 chunks -> 4 independent MUFU chains per lane
__global__ void k_rows() {
    const int gtid = blockIdx.x * blockDim.x + threadIdx.x;
    const int row  = gtid >> 5;
    const int lane = gtid & 31;
    if (row >= NB) return;

    const float neg = g_negsum[row];
    const int   np  = g_poscnt[row];
    const int   m   = np < MAXPOS ? np : MAXPOS;

    const float4* rowp = (const float4*)&g_pos[(size_t)row * MAXPOS];
    float s = 0.0f;
    for (int c = lane; c * 4 < m; c += 32) {
        float4 v = rowp[c];
        const int base = c * 4;
        float vv[4] = {v.x, v.y, v.z, v.w};
        #pragma unroll
        for (int k = 0; k < 4; k++) {
            if (base + k < m) {
                float e = ex2(vv[k] * LOG2E);
                s -= __logf(__fdividef(e, e + neg) + EPSL);
            }
        }
    }
    #pragma unroll
    for (int o = 16; o > 0; o >>= 1)
        s += __shfl_xor_sync(0xffffffffu, s, o);

    if (lane == 0) {
        const int nneg = NB - 1 - np;
        if (np > 0 && nneg > 0) {
            atomicAdd(&g_total, s / (float)np);
            atomicAdd(&g_nvalid, 1);
        }
    }
}

__global__ void k_out(float* out) {
    out[0] = (g_nvalid > 0) ? g_total / (float)g_nvalid : 0.0f;
}

// ---------------------------------------------------------------------------
extern "C" void kernel_launch(void* const* d_in, const int* in_sizes, int n_in,
                              void* d_out, int out_size) {
    const float* feats  = (const float*)d_in[0];
    const void*  labels = d_in[1];

    cudaFuncSetAttribute(k_main, cudaFuncAttributeMaxDynamicSharedMemorySize, SM_TOT);

    k_init<<<(NB + 255) / 256, 256>>>((const int*)labels);
    k_prep<<<(NB * ND / 4) / 256, 256>>>(feats);

    dim3 grid(NB / (NT * 128), NB / 128);   // (16, 64) = 1024 CTAs
    k_main<<<grid, 256, SM_TOT>>>(labels);

    k_rows<<<(NB * 32) / 256, 256>>>();
    k_out<<<1, 1>>>((float*)d_out);
}

// round 12
// speedup vs baseline: 5.1727x; 1.2440x over previous
#include <cuda_runtime.h>
#include <cuda_bf16.h>
#include <cstdint>

// Problem constants
#define NB      8192
#define ND      256
#define MAXPOS  1536
#define INV_T   14.285714285714286f
#define EXC     20.617439059314203f   // INV_T * log2(e)
#define LOG2E   1.4426950408889634f
#define EPSL    1e-8f
#define ROWSTR  272                   // smem row stride (256 fp8 + 16B pad)
#define NTILE_D 64                    // 8192/128 tile grid dim
#define NTILES  2080                  // 64*65/2 upper-tri tiles
#define GRIDM   296                   // k_main CTAs (2/SM on 148 SMs)

// ---- scratch (__device__ globals; no allocation) ----
__device__ float    g_negsum[NB];
__device__ int      g_poscnt[NB];
__device__ float    g_pos[(size_t)NB * MAXPOS];   // 48 MB
__device__ float    g_total;
__device__ int      g_nvalid;
__device__ int      g_lab[NB];
__device__ uint8_t  g_f8[(size_t)NB * ND];        // 2 MB e4m3 features

// ============================ helpers ============================
__device__ __forceinline__ uint32_t smem_u32(const void* p) {
    uint32_t a;
    asm("{ .reg .u64 t; cvta.to.shared.u64 t, %1; cvt.u32.u64 %0, t; }" : "=r"(a) : "l"(p));
    return a;
}
__device__ __forceinline__ void ldsm_x4(uint32_t* r, uint32_t addr) {
    asm volatile("ldmatrix.sync.aligned.m8n8.x4.shared.b16 {%0,%1,%2,%3}, [%4];"
                 : "=r"(r[0]), "=r"(r[1]), "=r"(r[2]), "=r"(r[3]) : "r"(addr));
}
__device__ __forceinline__ void mma_fp8(float* c, const uint32_t* a,
                                        uint32_t b0, uint32_t b1) {
    asm volatile(
        "mma.sync.aligned.m16n8k32.row.col.f32.e4m3.e4m3.f32 "
        "{%0,%1,%2,%3}, {%4,%5,%6,%7}, {%8,%9}, {%0,%1,%2,%3};"
        : "+f"(c[0]), "+f"(c[1]), "+f"(c[2]), "+f"(c[3])
        : "r"(a[0]), "r"(a[1]), "r"(a[2]), "r"(a[3]), "r"(b0), "r"(b1));
}
__device__ __forceinline__ void cp16(uint32_t dst, const void* src) {
    asm volatile("cp.async.cg.shared.global [%0], [%1], 16;" :: "r"(dst), "l"(src));
}
#define CP_COMMIT() asm volatile("cp.async.commit_group;" ::: "memory")
#define CP_WAIT0()  asm volatile("cp.async.wait_group 0;" ::: "memory")
__device__ __forceinline__ float ex2(float x) {
    float y; asm("ex2.approx.ftz.f32 %0, %1;" : "=f"(y) : "f"(x)); return y;
}
__device__ __forceinline__ uint16_t cvt8x2(float hi, float lo) {
    uint16_t h;
    asm("cvt.rn.satfinite.e4m3x2.f32 %0, %1, %2;" : "=h"(h) : "f"(hi), "f"(lo));
    return h;
}

// ============================ k_conv: fp8 convert + init ============================
// grid 2048 x 256. Block 0 additionally: detect label dtype, convert labels,
// zero totals. Threads with global idx < NB zero negsum/poscnt.
__global__ void k_conv(const float* __restrict__ f, const void* __restrict__ labels) {
    __shared__ int s_is64;
    const int gid = blockIdx.x * blockDim.x + threadIdx.x;

    float4 v = ((const float4*)f)[gid];
    uint32_t lo = cvt8x2(v.y, v.x);
    uint32_t hi = cvt8x2(v.w, v.z);
    ((uint32_t*)g_f8)[gid] = lo | (hi << 16);

    if (gid < NB) { g_negsum[gid] = 0.0f; g_poscnt[gid] = 0; }
    if (gid == 0) { g_total = 0.0f; g_nvalid = 0; }

    if (blockIdx.x == 0) {
        if (threadIdx.x == 0) {
            const int* l32 = (const int*)labels;
            int all0 = 1;
            #pragma unroll 1
            for (int t = 1; t < 128; t += 2)
                if (l32[t] != 0) { all0 = 0; break; }
            s_is64 = all0;
        }
        __syncthreads();
        const int is64 = s_is64;
        for (int i = threadIdx.x; i < NB; i += 256)
            g_lab[i] = is64 ? (int)((const long long*)labels)[i]
                            : ((const int*)labels)[i];
    }
}

// ============================ main fused kernel ============================
#define SM_A   0
#define SM_B0  (128 * ROWSTR)
#define SM_B1  (2 * 128 * ROWSTR)
#define SM_TOT (3 * 128 * ROWSTR)     // 104,448 B -> 2 CTAs/SM

extern __shared__ char dsm[];

__global__ void __launch_bounds__(256, 2) k_main() {
    const int tid  = threadIdx.x;
    const int warp = tid >> 5;
    const int lane = tid & 31;
    const int warpRow = warp & 3;          // 4 row-bands of 32
    const int warpCol = warp >> 2;         // 2 col-bands of 64

    // static contiguous chunk of upper-triangular tiles
    const int start = (int)(((long long)blockIdx.x * NTILES) / GRIDM);
    const int end   = (int)(((long long)(blockIdx.x + 1) * NTILES) / GRIDM);
    if (start >= end) return;

    // decode first tile: row I has (64-I) tiles, J in [I, 64)
    int I = 0, base = 0;
    while (base + (NTILE_D - I) <= start) { base += NTILE_D - I; I++; }
    int J = I + (start - base);

    const uint32_t smb = smem_u32(dsm);

    // fragment addresses (fp8 m16n8k32, layout validated in prior rounds)
    const uint32_t aBase = smb + SM_A
        + (uint32_t)(warpRow * 32 + ((lane >> 3) & 1) * 8 + (lane & 7)) * ROWSTR
        + (lane >> 4) * 16;
    const uint32_t bRowOff =
        (uint32_t)(warpCol * 64 + (lane >> 4) * 8 + (lane & 7)) * ROWSTR
        + ((lane >> 3) & 1) * 16;

    int rloc[4];
    #pragma unroll
    for (int idx = 0; idx < 4; idx++)
        rloc[idx] = warpRow * 32 + (idx >> 1) * 16 + (idx & 1) * 8 + (lane >> 2);

    // ---- prologue: load A(I) and B(J) ----
    {
        const uint4* srcA = (const uint4*)(g_f8 + (size_t)I * 128 * ND);
        const uint4* srcB = (const uint4*)(g_f8 + (size_t)J * 128 * ND);
        #pragma unroll
        for (int i = 0; i < 8; i++) {
            int u = tid + i * 256;
            int row = u >> 4, q = u & 15;
            cp16(smb + SM_A  + row * ROWSTR + q * 16, srcA + u);
            cp16(smb + SM_B0 + row * ROWSTR + q * 16, srcB + u);
        }
        CP_COMMIT();
    }

    for (int t = start; t < end; t++) {
        const int buf = (t - start) & 1;
        // next tile coords
        int nI = I, nJ = J + 1;
        if (nJ == NTILE_D) { nI = I + 1; nJ = nI; }
        const bool haveNext = (t + 1 < end);

        CP_WAIT0();
        __syncthreads();                       // A + B[buf] visible

        // ---- GEMM: 128x128 tile, K=256, warp tile 32x64 ----
        float acc[2][8][4];
        #pragma unroll
        for (int mt = 0; mt < 2; mt++)
            #pragma unroll
            for (int nt = 0; nt < 8; nt++)
                #pragma unroll
                for (int c = 0; c < 4; c++) acc[mt][nt][c] = 0.0f;

        const uint32_t bBase = (buf ? smb + SM_B1 : smb + SM_B0) + bRowOff;
        #pragma unroll
        for (int ks = 0; ks < 8; ks++) {
            const uint32_t koff = ks * 32;
            uint32_t a[2][4], b[4][4];
            ldsm_x4(a[0], aBase + koff);
            ldsm_x4(a[1], aBase + 16 * ROWSTR + koff);
            #pragma unroll
            for (int nt2 = 0; nt2 < 4; nt2++)
                ldsm_x4(b[nt2], bBase + nt2 * 16 * ROWSTR + koff);
            #pragma unroll
            for (int mt = 0; mt < 2; mt++)
                #pragma unroll
                for (int nt = 0; nt < 8; nt++)
                    mma_fp8(acc[mt][nt], a[mt],
                            b[nt >> 1][(nt & 1) * 2], b[nt >> 1][(nt & 1) * 2 + 1]);
        }

        __syncthreads();                       // all warps done reading A, B[buf]

        // ---- prefetch next tile (overlaps epilogue) ----
        if (haveNext) {
            const uint4* srcB = (const uint4*)(g_f8 + (size_t)nJ * 128 * ND);
            const uint32_t dstB = buf ? (smb + SM_B0) : (smb + SM_B1);
            #pragma unroll
            for (int i = 0; i < 8; i++) {
                int u = tid + i * 256;
                int row = u >> 4, q = u & 15;
                cp16(dstB + row * ROWSTR + q * 16, srcB + u);
            }
            if (nI != I) {
                const uint4* srcA = (const uint4*)(g_f8 + (size_t)nI * 128 * ND);
                #pragma unroll
                for (int i = 0; i < 8; i++) {
                    int u = tid + i * 256;
                    int row = u >> 4, q = u & 15;
                    cp16(smb + SM_A + row * ROWSTR + q * 16, srcA + u);
                }
            }
            CP_COMMIT();
        }

        // ---- epilogue: double-accounted classify/scatter ----
        const int rowBase = I * 128;
        const int colBase = J * 128;
        const bool diag   = (I == J);

        int lblC16[16];
        #pragma unroll
        for (int c2 = 0; c2 < 16; c2++) {
            const int col = warpCol * 64 + (c2 >> 1) * 8 + 2 * (lane & 3) + (c2 & 1);
            lblC16[c2] = g_lab[colBase + col];
        }

        #pragma unroll
        for (int idx = 0; idx < 4; idx++) {
            const int mt = idx >> 1, h = idx & 1;
            const int r    = rloc[idx];
            const int grow = rowBase + r;
            const int lr   = g_lab[grow];

            // classify: positive mask (skip diagonal lower-incl part)
            uint32_t pmask = 0;
            #pragma unroll
            for (int c2 = 0; c2 < 16; c2++) {
                const int col = warpCol * 64 + (c2 >> 1) * 8 + 2 * (lane & 3) + (c2 & 1);
                const bool skip = diag && (col <= r);
                if (!skip && lblC16[c2] == lr) pmask |= 1u << c2;
            }
            // scatter positives to BOTH rows' lists
            if (pmask) {
                int w = atomicAdd(&g_poscnt[grow], __popc(pmask));
                float* dstR = &g_pos[(size_t)grow * MAXPOS];
                uint32_t m = pmask;
                while (m) {
                    const int b = __ffs(m) - 1; m &= m - 1;
                    const float val = acc[mt][b >> 1][h * 2 + (b & 1)] * INV_T;
                    if (w < MAXPOS) dstR[w] = val;
                    w++;
                    const int col  = warpCol * 64 + (b >> 1) * 8 + 2 * (lane & 3) + (b & 1);
                    const int gcol = colBase + col;
                    int wc = atomicAdd(&g_poscnt[gcol], 1);
                    if (wc < MAXPOS) g_pos[(size_t)gcol * MAXPOS + wc] = val;
                }
            }
            // overwrite acc with exp (negatives) or 0 (positives / skipped)
            float rs = 0.0f;
            #pragma unroll
            for (int c2 = 0; c2 < 16; c2++) {
                const int col = warpCol * 64 + (c2 >> 1) * 8 + 2 * (lane & 3) + (c2 & 1);
                const bool skip = (diag && (col <= r)) || ((pmask >> c2) & 1);
                float* ap = &acc[mt][c2 >> 1][h * 2 + (c2 & 1)];
                const float e = skip ? 0.0f : ex2(*ap * EXC);
                *ap = e;
                rs += e;
            }
            // row-side neg sum: reduce over the 4 lanes sharing this row
            rs += __shfl_xor_sync(0xffffffffu, rs, 1);
            rs += __shfl_xor_sync(0xffffffffu, rs, 2);
            if ((lane & 3) == 0 && rs != 0.0f) atomicAdd(&g_negsum[grow], rs);
        }

        // column-side neg sums: reduce each column over the 8 row-lanes
        #pragma unroll
        for (int c2 = 0; c2 < 16; c2++) {
            float cs = acc[0][c2 >> 1][(c2 & 1)]     + acc[0][c2 >> 1][2 + (c2 & 1)]
                     + acc[1][c2 >> 1][(c2 & 1)]     + acc[1][c2 >> 1][2 + (c2 & 1)];
            cs += __shfl_xor_sync(0xffffffffu, cs, 4);
            cs += __shfl_xor_sync(0xffffffffu, cs, 8);
            cs += __shfl_xor_sync(0xffffffffu, cs, 16);
            if (lane < 4 && cs != 0.0f) {
                const int col = warpCol * 64 + (c2 >> 1) * 8 + 2 * lane + (c2 & 1);
                atomicAdd(&g_negsum[colBase + col], cs);
            }
        }

        I = nI; J = nJ;
    }
}

// ---------------------------------------------------------------------------
__global__ void k_rows() {
    const int gtid = blockIdx.x * blockDim.x + threadIdx.x;
    const int row  = gtid >> 5;
    const int lane = gtid & 31;
    if (row >= NB) return;

    const float neg = g_negsum[row];
    const int   np  = g_poscnt[row];
    const int   m   = np < MAXPOS ? np : MAXPOS;

    const float4* rowp = (const float4*)&g_pos[(size_t)row * MAXPOS];
    float s = 0.0f;
    for (int c = lane; c * 4 < m; c += 32) {
        float4 v = rowp[c];
        const int base = c * 4;
        float vv[4] = {v.x, v.y, v.z, v.w};
        #pragma unroll
        for (int k = 0; k < 4; k++) {
            if (base + k < m) {
                float e = ex2(vv[k] * LOG2E);
                s -= __logf(__fdividef(e, e + neg) + EPSL);
            }
        }
    }
    #pragma unroll
    for (int o = 16; o > 0; o >>= 1)
        s += __shfl_xor_sync(0xffffffffu, s, o);

    if (lane == 0) {
        const int nneg = NB - 1 - np;
        if (np > 0 && nneg > 0) {
            atomicAdd(&g_total, s / (float)np);
            atomicAdd(&g_nvalid, 1);
        }
    }
}

__global__ void k_out(float* out) {
    out[0] = (g_nvalid > 0) ? g_total / (float)g_nvalid : 0.0f;
}

// ---------------------------------------------------------------------------
extern "C" void kernel_launch(void* const* d_in, const int* in_sizes, int n_in,
                              void* d_out, int out_size) {
    const float* feats  = (const float*)d_in[0];
    const void*  labels = d_in[1];

    cudaFuncSetAttribute(k_main, cudaFuncAttributeMaxDynamicSharedMemorySize, SM_TOT);

    k_conv<<<(NB * ND / 4) / 256, 256>>>(feats, labels);
    k_main<<<GRIDM, 256, SM_TOT>>>();
    k_rows<<<(NB * 32) / 256, 256>>>();
    k_out<<<1, 1>>>((float*)d_out);
}